// round 16
// baseline (speedup 1.0000x reference)
#include <cuda_runtime.h>
#include <cuda_fp16.h>
#include <cstdint>

#define NN     2048
#define NODES  4096
#define RGS    64                     // row-groups (64 rows each)
#define CGS    8                      // col-groups (256 cols each)
#define NBLK   (RGS * CGS)            // 512 blocks for pre/iter
#define LOG2E  1.4426950408889634f

// ---------------- device scratch ----------------
__device__ __align__(16) __half g_hd[(size_t)NODES * NN]; // (F1-F0)/2 fp16, 16.8MB
__device__ __align__(16) float  g_tab[5][NODES];          // s1^0..s1^4 tables
__device__ __align__(16) float  g_AP[2][CGS][NODES];      // A partials, parity-buffered
__device__ __align__(16) float  g_BvP[2][RGS][NN];        // Bv partials, parity-buffered

__device__ __forceinline__ float ex2f(float x) {
    float r; asm("ex2.approx.f32 %0, %1;" : "=f"(r) : "f"(x)); return r;
}
__device__ __forceinline__ float frcp(float x) {
    float r; asm("rcp.approx.f32 %0, %1;" : "=f"(r) : "f"(x)); return r;
}
__device__ __forceinline__ __half2 tanh2(__half2 x) {     // native MUFU.TANH f16x2
    __half2 r;
    asm("tanh.approx.f16x2 %0, %1;"
        : "=r"(*(unsigned*)&r) : "r"(*(unsigned*)&x));
    return r;
}
__device__ __forceinline__ float sigmoid_safe(float z) {
    z = fminf(fmaxf(z, -30.0f), 30.0f);
    return frcp(1.0f + ex2f(-z * LOG2E));
}

// ---------------- pre: hd=(F1-F0)/2 (fp16) + matvec^0 via tanh f16x2 ----------
__global__ void __launch_bounds__(256) pre_kernel(
    const float* __restrict__ S, const float* __restrict__ F)
{
    const int tid = threadIdx.x;
    const int rg = blockIdx.x >> 3, cg = blockIdx.x & 7;
    const int rowBase = rg * 64;
    const int b = rowBase >> 11;
    const int ci = tid & 31, rs = tid >> 5;
    const int c8 = cg * 256 + ci * 8;
    const int gc = b * NN + c8;
    const int rBase = rowBase + rs * 8;

    float s0c[8], m[8];
#pragma unroll
    for (int j = 0; j < 8; j++)
        s0c[j] = 1.0f - sigmoid_safe(S[2 * (gc + j) + 1] - S[2 * (gc + j)]);
    float s0csum = ((s0c[0] + s0c[1]) + (s0c[2] + s0c[3])) +
                   ((s0c[4] + s0c[5]) + (s0c[6] + s0c[7]));
#pragma unroll
    for (int r = 0; r < 8; r++) {
        int row = rBase + r;
        m[r] = sigmoid_safe(S[2 * row + 1] - S[2 * row]);
    }
    float msum = ((m[0] + m[1]) + (m[2] + m[3])) + ((m[4] + m[5]) + (m[6] + m[7]));
    if (cg == 0 && tid < 64) {                   // materialize s1^0 table
        int i2 = rowBase + tid;
        g_tab[0][i2] = sigmoid_safe(S[2 * i2 + 1] - S[2 * i2]);
    }

    float colsum[8] = {0,0,0,0,0,0,0,0};         // accumulates t*m
    const float4* F4 = (const float4*)F;

#pragma unroll 2
    for (int r = 0; r < 8; r++) {
        const size_t row = rBase + r;
        const size_t fo = row * 1024 + (c8 >> 1);
        float4 f0 = __ldcs(&F4[fo + 0]);
        float4 f1 = __ldcs(&F4[fo + 1]);
        float4 f2 = __ldcs(&F4[fo + 2]);
        float4 f3 = __ldcs(&F4[fo + 3]);
        __half2 h[4];
        h[0] = __floats2half2_rn((f0.y - f0.x) * 0.5f, (f0.w - f0.z) * 0.5f);
        h[1] = __floats2half2_rn((f1.y - f1.x) * 0.5f, (f1.w - f1.z) * 0.5f);
        h[2] = __floats2half2_rn((f2.y - f2.x) * 0.5f, (f2.w - f2.z) * 0.5f);
        h[3] = __floats2half2_rn((f3.y - f3.x) * 0.5f, (f3.w - f3.z) * 0.5f);
        uint4 st;
        st.x = *(unsigned*)&h[0]; st.y = *(unsigned*)&h[1];
        st.z = *(unsigned*)&h[2]; st.w = *(unsigned*)&h[3];
        *(uint4*)&g_hd[row * NN + c8] = st;

        float ra = 0.0f;                         // accumulates t*s0c
#pragma unroll
        for (int jj = 0; jj < 4; jj++) {
            float2 tf = __half22float2(tanh2(h[jj]));   // q = 0.5 + 0.5*t
            ra = fmaf(tf.x, s0c[2 * jj], ra);
            ra = fmaf(tf.y, s0c[2 * jj + 1], ra);
            colsum[2 * jj]     = fmaf(tf.x, m[r], colsum[2 * jj]);
            colsum[2 * jj + 1] = fmaf(tf.y, m[r], colsum[2 * jj + 1]);
        }
        ra = 0.5f * (s0csum + ra);
        ra += __shfl_down_sync(~0u, ra, 16);
        ra += __shfl_down_sync(~0u, ra, 8);
        ra += __shfl_down_sync(~0u, ra, 4);
        ra += __shfl_down_sync(~0u, ra, 2);
        ra += __shfl_down_sync(~0u, ra, 1);
        if (ci == 0) g_AP[0][cg][row] = ra;
    }

    __shared__ float sh[8][256];
#pragma unroll
    for (int j = 0; j < 8; j++) sh[rs][ci * 8 + j] = 0.5f * (msum + colsum[j]);
    __syncthreads();
    float v = 0.0f;
#pragma unroll
    for (int s = 0; s < 8; s++) v += sh[s][tid];
    g_BvP[0][rg][cg * 256 + tid] = v;
    cudaTriggerProgrammaticLaunchCompletion();
}

// ---------------- iter j=1..4: fused node recompute + tanh f16x2 matvec -------
__global__ void __launch_bounds__(256, 4) iter_kernel(
    const float* __restrict__ S, const float* __restrict__ C,
    const float* __restrict__ W, int j)
{
    const int tid = threadIdx.x;
    const int rg = blockIdx.x >> 3, cg = blockIdx.x & 7;
    const int rowBase = rg * 64;
    const int b = rowBase >> 11;
    const int ci = tid & 31, rs = tid >> 5;
    const int c8 = cg * 256 + ci * 8;
    const int gc = b * NN + c8;
    const int rBase = rowBase + rs * 8;
    const int rp = (j - 1) & 1, wp = j & 1;
    const int jm2 = (j >= 2) ? j - 2 : 0;
    const float w0 = W[0], w1 = W[1];

    // ---- PDL prologue: input-only loads (S, C are harness inputs) ----
    const int icol = b * NN + cg * 256 + tid;
    const float SdC = S[2 * icol + 1] - S[2 * icol];
    const float CdC = C[2 * icol] - C[2 * icol + 1];
    float SdR = 0.0f, CdR = 0.0f;
    if (tid < 64) {
        const int i2 = rowBase + tid;
        SdR = S[2 * i2 + 1] - S[2 * i2];
        CdR = C[2 * i2] - C[2 * i2 + 1];
    }
    cudaGridDependencySynchronize();             // wait for predecessor's writes

    // ---- hoisted loads: hd tile (immutable) + s1^{j-1} (sealed last launch) --
    uint4 dv[8];
    const __half* dp = g_hd + (size_t)rBase * NN + c8;
#pragma unroll
    for (int r = 0; r < 8; r++)
        dv[r] = *(const uint4*)(dp + (size_t)r * NN);
    float4 p0 = *(const float4*)&g_tab[j - 1][gc];
    float4 p1 = *(const float4*)&g_tab[j - 1][gc + 4];
    float s1p_row[8];
#pragma unroll
    for (int r = 0; r < 8; r++)
        s1p_row[r] = g_tab[j - 1][rBase + r];

    // ---- redundant node update: s1^j for my 256 cols + 64 rows ----
    __shared__ float smc[256], smr[64];
    {
        float bv = 0.0f;
#pragma unroll
        for (int t = 0; t < 32; t++) bv += g_BvP[rp][b * 32 + t][cg * 256 + tid];
        float Av = 0.0f;
#pragma unroll
        for (int g = 0; g < CGS; g++) Av += g_AP[rp][g][icol];
        float c0 = (j == 1) ? sigmoid_safe(CdC)
                            : sigmoid_safe(CdC - w0 * g_tab[jm2][icol]);
        smc[tid] = sigmoid_safe(SdC + w1 * bv - w0 * c0 - w1 * Av);
    }
    if (tid < 64) {
        const int i2 = rowBase + tid;
        const int c2 = i2 & (NN - 1);
        float bv = 0.0f;
#pragma unroll
        for (int t = 0; t < 32; t++) bv += g_BvP[rp][b * 32 + t][c2];
        float Av = 0.0f;
#pragma unroll
        for (int g = 0; g < CGS; g++) Av += g_AP[rp][g][i2];
        float c0 = (j == 1) ? sigmoid_safe(CdR)
                            : sigmoid_safe(CdR - w0 * g_tab[jm2][i2]);
        float vv = sigmoid_safe(SdR + w1 * bv - w0 * c0 - w1 * Av);
        smr[tid] = vv;
        if (cg == 0) g_tab[j][i2] = vv;
    }
    __syncthreads();

    // ---- mainloop: q = 0.5 + 0.5*tanh(hd - (w1*s1p/2)*s0p) ----
    float s0c[8], m[8];
#pragma unroll
    for (int q = 0; q < 8; q++) s0c[q] = 1.0f - smc[ci * 8 + q];
    float s0csum = ((s0c[0] + s0c[1]) + (s0c[2] + s0c[3])) +
                   ((s0c[4] + s0c[5]) + (s0c[6] + s0c[7]));
    __half2 s0ph[4];
    s0ph[0] = __floats2half2_rn(1.f - p0.x, 1.f - p0.y);
    s0ph[1] = __floats2half2_rn(1.f - p0.z, 1.f - p0.w);
    s0ph[2] = __floats2half2_rn(1.f - p1.x, 1.f - p1.y);
    s0ph[3] = __floats2half2_rn(1.f - p1.z, 1.f - p1.w);
    float a2[8];
#pragma unroll
    for (int r = 0; r < 8; r++) {
        a2[r] = -0.5f * w1 * s1p_row[r];             // negated half-scale
        m[r]  = smr[rs * 8 + r];
    }
    float msum = ((m[0] + m[1]) + (m[2] + m[3])) + ((m[4] + m[5]) + (m[6] + m[7]));

    float colsum[8] = {0,0,0,0,0,0,0,0};    // accumulates t*m
#pragma unroll
    for (int r = 0; r < 8; r++) {
        const __half2 a2h = __float2half2_rn(a2[r]);
        const __half2* hd2 = (const __half2*)&dv[r];
        float ra = 0.0f;                    // accumulates t*s0c
#pragma unroll
        for (int jj = 0; jj < 4; jj++) {
            __half2 z2 = __hfma2(a2h, s0ph[jj], hd2[jj]);
            float2 tf = __half22float2(tanh2(z2));
            ra = fmaf(tf.x, s0c[2 * jj], ra);
            ra = fmaf(tf.y, s0c[2 * jj + 1], ra);
            colsum[2 * jj]     = fmaf(tf.x, m[r], colsum[2 * jj]);
            colsum[2 * jj + 1] = fmaf(tf.y, m[r], colsum[2 * jj + 1]);
        }
        ra = 0.5f * (s0csum + ra);
        ra += __shfl_down_sync(~0u, ra, 16);
        ra += __shfl_down_sync(~0u, ra, 8);
        ra += __shfl_down_sync(~0u, ra, 4);
        ra += __shfl_down_sync(~0u, ra, 2);
        ra += __shfl_down_sync(~0u, ra, 1);
        if (ci == 0) g_AP[wp][cg][rBase + r] = ra;
    }

    __shared__ float sh[8][256];
#pragma unroll
    for (int q = 0; q < 8; q++) sh[rs][ci * 8 + q] = 0.5f * (msum + colsum[q]);
    __syncthreads();
    float v = 0.0f;
#pragma unroll
    for (int s = 0; s < 8; s++) v += sh[s][tid];
    g_BvP[wp][rg][cg * 256 + tid] = v;
    cudaTriggerProgrammaticLaunchCompletion();
}

// ---------------- final: 2 rows/block, F outputs + fused reductions + S/C -----
// out floats: [S: 8192][C: 8192][F: 16777216]; s1^4=g_tab[4], s1^3=g_tab[3]
__global__ void __launch_bounds__(256) final_kernel(
    const float* __restrict__ S, const float* __restrict__ C,
    const float* __restrict__ F, const float* __restrict__ W,
    float* __restrict__ out)
{
    const int r0 = blockIdx.x * 2;               // grid 2048
    const int b = r0 >> 11;
    const int tid = threadIdx.x;
    const float w0 = W[0], w1 = W[1];
    const float4* Fr = (const float4*)F + (size_t)r0 * 1024;
    float4* Or = (float4*)out + 4096 + (size_t)r0 * 1024;

    // ---- PDL prologue: start the big F read early (F is a harness input) ----
    float4 f[8];
#pragma unroll
    for (int u = 0; u < 4; u++) {                // front-batch 8 loads (2 rows)
        int i = tid + 256 * u;
        f[u]     = __ldcs(&Fr[i]);
        f[u + 4] = __ldcs(&Fr[i + 1024]);
    }
    cudaGridDependencySynchronize();             // wait for iter4's writes

    const float a0 = w1 * g_tab[4][r0];
    const float a1 = w1 * g_tab[4][r0 + 1];
    const float* s1col = &g_tab[4][b * NN];
    float2 s[4];
#pragma unroll
    for (int u = 0; u < 4; u++) {
        int i = tid + 256 * u;
        s[u] = *(const float2*)&s1col[2 * i];
    }
#pragma unroll
    for (int u = 0; u < 4; u++) {
        int i = tid + 256 * u;
        float e0 = 1.0f - s[u].x, e1 = 1.0f - s[u].y;
        f[u].x = fmaf(a0, e0, f[u].x);
        f[u].z = fmaf(a0, e1, f[u].z);
        f[u + 4].x = fmaf(a1, e0, f[u + 4].x);
        f[u + 4].z = fmaf(a1, e1, f[u + 4].z);
        __stcs(&Or[i], f[u]);
        __stcs(&Or[i + 1024], f[u + 4]);
    }
    if (blockIdx.x < 16) {
        const int i = blockIdx.x * 256 + tid;
        const int bb = i >> 11, c = i & (NN - 1);
        float bv = 0.0f;
#pragma unroll
        for (int t = 0; t < 32; t++) bv += g_BvP[0][bb * 32 + t][c];
        float Av = 0.0f;
#pragma unroll
        for (int g = 0; g < CGS; g++) Av += g_AP[0][g][i];

        float s13 = g_tab[3][i], s14 = g_tab[4][i];
        float Cd = C[2 * i] - C[2 * i + 1];
        float c04 = sigmoid_safe(Cd - w0 * s13);
        out[2 * i]     = S[2 * i] + w0 * c04 + w1 * Av;
        out[2 * i + 1] = S[2 * i + 1] + w1 * bv;
        out[8192 + 2 * i]     = C[2 * i];
        out[8192 + 2 * i + 1] = C[2 * i + 1] + w0 * s14;
    }
}

// ---------------- host: PDL launches ------------------------------------------
template <typename... Args>
static void launch_pdl(void (*fn)(Args...), int grid, int block, Args... args)
{
    cudaLaunchConfig_t cfg = {};
    cfg.gridDim = dim3(grid, 1, 1);
    cfg.blockDim = dim3(block, 1, 1);
    cudaLaunchAttribute attr[1];
    attr[0].id = cudaLaunchAttributeProgrammaticStreamSerialization;
    attr[0].val.programmaticStreamSerializationAllowed = 1;
    cfg.attrs = attr;
    cfg.numAttrs = 1;
    cudaLaunchKernelEx(&cfg, fn, args...);
}

extern "C" void kernel_launch(void* const* d_in, const int* in_sizes, int n_in,
                              void* d_out, int out_size)
{
    const float* S = (const float*)d_in[0];
    const float* C = (const float*)d_in[1];
    const float* F = (const float*)d_in[2];
    const float* W = (const float*)d_in[3];
    float* out = (float*)d_out;

    pre_kernel<<<NBLK, 256>>>(S, F);                       // hd + matvec^0
    for (int j = 1; j <= 4; j++)
        launch_pdl(iter_kernel, NBLK, 256, S, C, W, j);    // s1^j + matvec^j
    launch_pdl(final_kernel, 2048, 256, S, C, F, W, out);  // outputs + reduce
}

// round 17
// speedup vs baseline: 1.3207x; 1.3207x over previous
#include <cuda_runtime.h>
#include <cuda_fp16.h>
#include <cstdint>

#define NN     2048
#define NODES  4096
#define RGS    64                     // row-groups (64 rows each)
#define CGS    8                      // col-groups (256 cols each)
#define NBLK   (RGS * CGS)            // 512 blocks for pre/iter
#define LOG2E  1.4426950408889634f

// ---------------- device scratch ----------------
__device__ __align__(16) __half g_hd[(size_t)NODES * NN]; // (F1-F0)/2 fp16, 16.8MB
__device__ __align__(16) float  g_tab[5][NODES];          // s1^0..s1^4 tables
__device__ __align__(16) float  g_AP[2][CGS][NODES];      // A partials, parity-buffered
__device__ __align__(16) float  g_BvP[2][RGS][NN];        // Bv partials, parity-buffered

__device__ __forceinline__ float ex2f(float x) {
    float r; asm("ex2.approx.f32 %0, %1;" : "=f"(r) : "f"(x)); return r;
}
__device__ __forceinline__ float frcp(float x) {
    float r; asm("rcp.approx.f32 %0, %1;" : "=f"(r) : "f"(x)); return r;
}
__device__ __forceinline__ __half2 tanh2(__half2 x) {     // native MUFU.TANH f16x2
    __half2 r;
    asm("tanh.approx.f16x2 %0, %1;"
        : "=r"(*(unsigned*)&r) : "r"(*(unsigned*)&x));
    return r;
}
__device__ __forceinline__ float sigmoid_safe(float z) {
    z = fminf(fmaxf(z, -30.0f), 30.0f);
    return frcp(1.0f + ex2f(-z * LOG2E));
}

// ---------------- pre: hd=(F1-F0)/2 (fp16) + matvec^0 via tanh f16x2 ----------
__global__ void __launch_bounds__(256) pre_kernel(
    const float* __restrict__ S, const float* __restrict__ F)
{
    const int tid = threadIdx.x;
    const int rg = blockIdx.x >> 3, cg = blockIdx.x & 7;
    const int rowBase = rg * 64;
    const int b = rowBase >> 11;
    const int ci = tid & 31, rs = tid >> 5;
    const int c8 = cg * 256 + ci * 8;
    const int gc = b * NN + c8;
    const int rBase = rowBase + rs * 8;

    float s0c[8], m[8];
#pragma unroll
    for (int j = 0; j < 8; j++)
        s0c[j] = 1.0f - sigmoid_safe(S[2 * (gc + j) + 1] - S[2 * (gc + j)]);
    float s0csum = ((s0c[0] + s0c[1]) + (s0c[2] + s0c[3])) +
                   ((s0c[4] + s0c[5]) + (s0c[6] + s0c[7]));
#pragma unroll
    for (int r = 0; r < 8; r++) {
        int row = rBase + r;
        m[r] = sigmoid_safe(S[2 * row + 1] - S[2 * row]);
    }
    float msum = ((m[0] + m[1]) + (m[2] + m[3])) + ((m[4] + m[5]) + (m[6] + m[7]));
    if (cg == 0 && tid < 64) {                   // materialize s1^0 table
        int i2 = rowBase + tid;
        g_tab[0][i2] = sigmoid_safe(S[2 * i2 + 1] - S[2 * i2]);
    }

    float colsum[8] = {0,0,0,0,0,0,0,0};         // accumulates t*m
    const float4* F4 = (const float4*)F;

#pragma unroll 2
    for (int r = 0; r < 8; r++) {
        const size_t row = rBase + r;
        const size_t fo = row * 1024 + (c8 >> 1);
        float4 f0 = __ldcs(&F4[fo + 0]);
        float4 f1 = __ldcs(&F4[fo + 1]);
        float4 f2 = __ldcs(&F4[fo + 2]);
        float4 f3 = __ldcs(&F4[fo + 3]);
        __half2 h[4];
        h[0] = __floats2half2_rn((f0.y - f0.x) * 0.5f, (f0.w - f0.z) * 0.5f);
        h[1] = __floats2half2_rn((f1.y - f1.x) * 0.5f, (f1.w - f1.z) * 0.5f);
        h[2] = __floats2half2_rn((f2.y - f2.x) * 0.5f, (f2.w - f2.z) * 0.5f);
        h[3] = __floats2half2_rn((f3.y - f3.x) * 0.5f, (f3.w - f3.z) * 0.5f);
        uint4 st;
        st.x = *(unsigned*)&h[0]; st.y = *(unsigned*)&h[1];
        st.z = *(unsigned*)&h[2]; st.w = *(unsigned*)&h[3];
        *(uint4*)&g_hd[row * NN + c8] = st;

        float ra = 0.0f;                         // accumulates t*s0c
#pragma unroll
        for (int jj = 0; jj < 4; jj++) {
            float2 tf = __half22float2(tanh2(h[jj]));   // q = 0.5 + 0.5*t
            ra = fmaf(tf.x, s0c[2 * jj], ra);
            ra = fmaf(tf.y, s0c[2 * jj + 1], ra);
            colsum[2 * jj]     = fmaf(tf.x, m[r], colsum[2 * jj]);
            colsum[2 * jj + 1] = fmaf(tf.y, m[r], colsum[2 * jj + 1]);
        }
        ra = 0.5f * (s0csum + ra);
        ra += __shfl_down_sync(~0u, ra, 16);
        ra += __shfl_down_sync(~0u, ra, 8);
        ra += __shfl_down_sync(~0u, ra, 4);
        ra += __shfl_down_sync(~0u, ra, 2);
        ra += __shfl_down_sync(~0u, ra, 1);
        if (ci == 0) g_AP[0][cg][row] = ra;
    }

    __shared__ float sh[8][256];
#pragma unroll
    for (int j = 0; j < 8; j++) sh[rs][ci * 8 + j] = 0.5f * (msum + colsum[j]);
    __syncthreads();
    float v = 0.0f;
#pragma unroll
    for (int s = 0; s < 8; s++) v += sh[s][tid];
    g_BvP[0][rg][cg * 256 + tid] = v;
    cudaTriggerProgrammaticLaunchCompletion();
}

// ---------------- iter j=1..4: fused node recompute + tanh f16x2 matvec -------
__global__ void __launch_bounds__(256) iter_kernel(
    const float* __restrict__ S, const float* __restrict__ C,
    const float* __restrict__ W, int j)
{
    const int tid = threadIdx.x;
    const int rg = blockIdx.x >> 3, cg = blockIdx.x & 7;
    const int rowBase = rg * 64;
    const int b = rowBase >> 11;
    const int ci = tid & 31, rs = tid >> 5;
    const int c8 = cg * 256 + ci * 8;
    const int gc = b * NN + c8;
    const int rBase = rowBase + rs * 8;
    const int rp = (j - 1) & 1, wp = j & 1;
    const int jm2 = (j >= 2) ? j - 2 : 0;
    const float w0 = W[0], w1 = W[1];

    // ---- PDL prologue: input-only loads (S, C are harness inputs) ----
    const int icol = b * NN + cg * 256 + tid;
    const float SdC = S[2 * icol + 1] - S[2 * icol];
    const float CdC = C[2 * icol] - C[2 * icol + 1];
    float SdR = 0.0f, CdR = 0.0f;
    if (tid < 64) {
        const int i2 = rowBase + tid;
        SdR = S[2 * i2 + 1] - S[2 * i2];
        CdR = C[2 * i2] - C[2 * i2 + 1];
    }
    cudaGridDependencySynchronize();             // wait for predecessor's writes

    // ---- redundant node update: s1^j for my 256 cols + 64 rows ----
    __shared__ float smc[256], smr[64];
    {
        float bv = 0.0f;
#pragma unroll
        for (int t = 0; t < 32; t++) bv += g_BvP[rp][b * 32 + t][cg * 256 + tid];
        float Av = 0.0f;
#pragma unroll
        for (int g = 0; g < CGS; g++) Av += g_AP[rp][g][icol];
        float c0 = (j == 1) ? sigmoid_safe(CdC)
                            : sigmoid_safe(CdC - w0 * g_tab[jm2][icol]);
        smc[tid] = sigmoid_safe(SdC + w1 * bv - w0 * c0 - w1 * Av);
    }
    if (tid < 64) {
        const int i2 = rowBase + tid;
        const int c2 = i2 & (NN - 1);
        float bv = 0.0f;
#pragma unroll
        for (int t = 0; t < 32; t++) bv += g_BvP[rp][b * 32 + t][c2];
        float Av = 0.0f;
#pragma unroll
        for (int g = 0; g < CGS; g++) Av += g_AP[rp][g][i2];
        float c0 = (j == 1) ? sigmoid_safe(CdR)
                            : sigmoid_safe(CdR - w0 * g_tab[jm2][i2]);
        float vv = sigmoid_safe(SdR + w1 * bv - w0 * c0 - w1 * Av);
        smr[tid] = vv;
        if (cg == 0) g_tab[j][i2] = vv;
    }

    // ---- prefetch: issue d-tile loads before the barrier so they fly during
    // the sync + setup (hd is immutable; g_tab[j-1] sealed by predecessor) ----
    uint4 dv[8];
    const __half* dp = g_hd + (size_t)rBase * NN + c8;
#pragma unroll
    for (int r = 0; r < 8; r++)
        dv[r] = *(const uint4*)(dp + (size_t)r * NN);
    float4 p0 = *(const float4*)&g_tab[j - 1][gc];
    float4 p1 = *(const float4*)&g_tab[j - 1][gc + 4];
    float s1p_row[8];
#pragma unroll
    for (int r = 0; r < 8; r++)
        s1p_row[r] = g_tab[j - 1][rBase + r];

    __syncthreads();

    // ---- mainloop: q = 0.5 + 0.5*tanh(hd - (w1*s1p/2)*s0p) ----
    float s0c[8], m[8];
#pragma unroll
    for (int q = 0; q < 8; q++) s0c[q] = 1.0f - smc[ci * 8 + q];
    float s0csum = ((s0c[0] + s0c[1]) + (s0c[2] + s0c[3])) +
                   ((s0c[4] + s0c[5]) + (s0c[6] + s0c[7]));
    __half2 s0ph[4];
    s0ph[0] = __floats2half2_rn(1.f - p0.x, 1.f - p0.y);
    s0ph[1] = __floats2half2_rn(1.f - p0.z, 1.f - p0.w);
    s0ph[2] = __floats2half2_rn(1.f - p1.x, 1.f - p1.y);
    s0ph[3] = __floats2half2_rn(1.f - p1.z, 1.f - p1.w);
    float a2[8];
#pragma unroll
    for (int r = 0; r < 8; r++) {
        a2[r] = -0.5f * w1 * s1p_row[r];             // negated half-scale
        m[r]  = smr[rs * 8 + r];
    }
    float msum = ((m[0] + m[1]) + (m[2] + m[3])) + ((m[4] + m[5]) + (m[6] + m[7]));

    float colsum[8] = {0,0,0,0,0,0,0,0};    // accumulates t*m
#pragma unroll
    for (int r = 0; r < 8; r++) {
        const __half2 a2h = __float2half2_rn(a2[r]);
        const __half2* hd2 = (const __half2*)&dv[r];
        float ra = 0.0f;                    // accumulates t*s0c
#pragma unroll
        for (int jj = 0; jj < 4; jj++) {
            __half2 z2 = __hfma2(a2h, s0ph[jj], hd2[jj]);
            float2 tf = __half22float2(tanh2(z2));
            ra = fmaf(tf.x, s0c[2 * jj], ra);
            ra = fmaf(tf.y, s0c[2 * jj + 1], ra);
            colsum[2 * jj]     = fmaf(tf.x, m[r], colsum[2 * jj]);
            colsum[2 * jj + 1] = fmaf(tf.y, m[r], colsum[2 * jj + 1]);
        }
        ra = 0.5f * (s0csum + ra);
        ra += __shfl_down_sync(~0u, ra, 16);
        ra += __shfl_down_sync(~0u, ra, 8);
        ra += __shfl_down_sync(~0u, ra, 4);
        ra += __shfl_down_sync(~0u, ra, 2);
        ra += __shfl_down_sync(~0u, ra, 1);
        if (ci == 0) g_AP[wp][cg][rBase + r] = ra;
    }

    __shared__ float sh[8][256];
#pragma unroll
    for (int q = 0; q < 8; q++) sh[rs][ci * 8 + q] = 0.5f * (msum + colsum[q]);
    __syncthreads();
    float v = 0.0f;
#pragma unroll
    for (int s = 0; s < 8; s++) v += sh[s][tid];
    g_BvP[wp][rg][cg * 256 + tid] = v;
    cudaTriggerProgrammaticLaunchCompletion();
}

// ---------------- final: 2 rows/block, F outputs + fused reductions + S/C -----
// out floats: [S: 8192][C: 8192][F: 16777216]; s1^4=g_tab[4], s1^3=g_tab[3]
__global__ void __launch_bounds__(256) final_kernel(
    const float* __restrict__ S, const float* __restrict__ C,
    const float* __restrict__ F, const float* __restrict__ W,
    float* __restrict__ out)
{
    const int r0 = blockIdx.x * 2;               // grid 2048
    const int b = r0 >> 11;
    const int tid = threadIdx.x;
    const float w0 = W[0], w1 = W[1];
    const float4* Fr = (const float4*)F + (size_t)r0 * 1024;
    float4* Or = (float4*)out + 4096 + (size_t)r0 * 1024;

    // ---- PDL prologue: start the big F read early (F is a harness input) ----
    float4 f[8];
#pragma unroll
    for (int u = 0; u < 4; u++) {                // front-batch 8 loads (2 rows)
        int i = tid + 256 * u;
        f[u]     = __ldcs(&Fr[i]);
        f[u + 4] = __ldcs(&Fr[i + 1024]);
    }
    cudaGridDependencySynchronize();             // wait for iter4's writes

    const float a0 = w1 * g_tab[4][r0];
    const float a1 = w1 * g_tab[4][r0 + 1];
    const float* s1col = &g_tab[4][b * NN];
    float2 s[4];
#pragma unroll
    for (int u = 0; u < 4; u++) {
        int i = tid + 256 * u;
        s[u] = *(const float2*)&s1col[2 * i];
    }
#pragma unroll
    for (int u = 0; u < 4; u++) {
        int i = tid + 256 * u;
        float e0 = 1.0f - s[u].x, e1 = 1.0f - s[u].y;
        f[u].x = fmaf(a0, e0, f[u].x);
        f[u].z = fmaf(a0, e1, f[u].z);
        f[u + 4].x = fmaf(a1, e0, f[u + 4].x);
        f[u + 4].z = fmaf(a1, e1, f[u + 4].z);
        __stcs(&Or[i], f[u]);
        __stcs(&Or[i + 1024], f[u + 4]);
    }
    if (blockIdx.x < 16) {
        const int i = blockIdx.x * 256 + tid;
        const int bb = i >> 11, c = i & (NN - 1);
        float bv = 0.0f;
#pragma unroll
        for (int t = 0; t < 32; t++) bv += g_BvP[0][bb * 32 + t][c];
        float Av = 0.0f;
#pragma unroll
        for (int g = 0; g < CGS; g++) Av += g_AP[0][g][i];

        float s13 = g_tab[3][i], s14 = g_tab[4][i];
        float Cd = C[2 * i] - C[2 * i + 1];
        float c04 = sigmoid_safe(Cd - w0 * s13);
        out[2 * i]     = S[2 * i] + w0 * c04 + w1 * Av;
        out[2 * i + 1] = S[2 * i + 1] + w1 * bv;
        out[8192 + 2 * i]     = C[2 * i];
        out[8192 + 2 * i + 1] = C[2 * i + 1] + w0 * s14;
    }
}

// ---------------- host: PDL launches ------------------------------------------
template <typename... Args>
static void launch_pdl(void (*fn)(Args...), int grid, int block, Args... args)
{
    cudaLaunchConfig_t cfg = {};
    cfg.gridDim = dim3(grid, 1, 1);
    cfg.blockDim = dim3(block, 1, 1);
    cudaLaunchAttribute attr[1];
    attr[0].id = cudaLaunchAttributeProgrammaticStreamSerialization;
    attr[0].val.programmaticStreamSerializationAllowed = 1;
    cfg.attrs = attr;
    cfg.numAttrs = 1;
    cudaLaunchKernelEx(&cfg, fn, args...);
}

extern "C" void kernel_launch(void* const* d_in, const int* in_sizes, int n_in,
                              void* d_out, int out_size)
{
    const float* S = (const float*)d_in[0];
    const float* C = (const float*)d_in[1];
    const float* F = (const float*)d_in[2];
    const float* W = (const float*)d_in[3];
    float* out = (float*)d_out;

    pre_kernel<<<NBLK, 256>>>(S, F);                       // hd + matvec^0
    for (int j = 1; j <= 4; j++)
        launch_pdl(iter_kernel, NBLK, 256, S, C, W, j);    // s1^j + matvec^j
    launch_pdl(final_kernel, 2048, 256, S, C, F, W, out);  // outputs + reduce
}